// round 9
// baseline (speedup 1.0000x reference)
#include <cuda_runtime.h>
#include <math.h>
#include <stdint.h>

// RVQE: 12-qubit real statevector recurrent cell, B=64, T=9 (8 scan steps).
// One CTA per batch element; state = 4096 floats = 256 threads x 8 packed f32x2.
// Global amplitude index g12 (12 bits), g12 = (t << 4) | r:
//   r bits: bit0=lane11(anc1), bit1=lane10(anc0), bit2=lane9, bit3=lane8
//   t bits 0..4 (warp lane): lanes 7,6,5,4,3  -> __shfl_xor (mask 1<<(7-lane))
//   t bits 5,6,7: lanes 2,1,0 -> smem exchange
// PACKING: P[j], j = a*4 + i, i = (anc0<<1)|anc1, a = lane8 bit.
//   P[j].lo = lane9=0, P[j].hi = lane9=1. All rotations are packed f32x2 FMA.
//
// Barrier discipline (this round): NO full __syncthreads inside a stage.
//   ry_smem4: 4-warp groups {w,w^2,w^4,w^6} -> bar.sync 13+(w&1),128 (x2)
//   ry_smem1: pair {w,w^1}                  -> bar.sync 9+((w>>1)&3),64
//   ciy n=0:  pair {w,w^4}, buf p128        -> bar.sync 1+(w&3),64
//   ciy n=1:  pair {w,w^2}, buf p64         -> bar.sync 5+((w&1)|((w>>1)&2)),64
//   ciy n=2:  pair {w,w^1}, buf p32         -> bar.sync 9+((w>>1)&3),64
// Cross-stage buffer-reuse hazards are ordered by shared group/pair barriers
// (each buffer's readers are exactly the partner set of its barrier) or
// transitively via the bit7->bit6->bit5 ciy butterfly (full closure over 8
// warps). Per-step full sync only around probs/projection.

namespace {

typedef unsigned long long u64;

constexpr int NTH   = 256;
constexpr int TT    = 9;
constexpr int NSTEP = 8;
constexpr int NIDX  = 22;   // 18 deltas + 2 entries + 2 trailings
constexpr int STq   = 9;    // exch stride in u64 (bank-pair stride 9, gcd(9,16)=1)
constexpr int CPq   = 5;    // ciy buffer stride in u64 (bank-pair stride 5)
constexpr u64 SGN2  = 0x8000000080000000ULL;

// dynamic smem layout (u64 units)
constexpr int OFF_EXCH = 0;
constexpr int OFF_P128 = NTH * STq;              // 2304
constexpr int OFF_P64  = OFF_P128 + NTH * CPq;   // +1280
constexpr int OFF_P32  = OFF_P64  + NTH * CPq;
constexpr int DYN_U64  = OFF_P32  + NTH * CPq;   // 6144 u64 = 49152 B

#define NBAR64(id)  asm volatile("bar.sync %0, 64;"  :: "r"(id) : "memory")
#define NBAR128(id) asm volatile("bar.sync %0, 128;" :: "r"(id) : "memory")

__device__ __forceinline__ u64 pk(float lo, float hi) {
    u64 r; asm("mov.b64 %0,{%1,%2};" : "=l"(r) : "f"(lo), "f"(hi)); return r;
}
__device__ __forceinline__ void upk(u64 u, float& lo, float& hi) {
    asm("mov.b64 {%0,%1},%2;" : "=f"(lo), "=f"(hi) : "l"(u));
}
__device__ __forceinline__ u64 bc(float x) { return pk(x, x); }
__device__ __forceinline__ u64 f2mul(u64 a, u64 b) {
    u64 d; asm("mul.rn.f32x2 %0,%1,%2;" : "=l"(d) : "l"(a), "l"(b)); return d;
}
__device__ __forceinline__ u64 f2fma(u64 a, u64 b, u64 c) {
    u64 d; asm("fma.rn.f32x2 %0,%1,%2,%3;" : "=l"(d) : "l"(a), "l"(b), "l"(c)); return d;
}
__device__ __forceinline__ u64 f2neg(u64 a) { return a ^ SGN2; }
__device__ __forceinline__ u64 f2swap(u64 a) { float lo, hi; upk(a, lo, hi); return pk(hi, lo); }

// ---- stage RY pieces ----

__device__ __forceinline__ void ry_lane9(u64* P, u64 C, u64 SW) {
#pragma unroll
    for (int j = 0; j < 8; j++)
        P[j] = f2fma(SW, f2swap(P[j]), f2mul(C, P[j]));
}

__device__ __forceinline__ void ry_lane8(u64* P, float c, float s) {
    u64 C = bc(c), S = bc(s), NS = bc(-s);
#pragma unroll
    for (int i = 0; i < 4; i++) {
        u64 u = P[i], w = P[4 + i];
        P[i]     = f2fma(NS, w, f2mul(C, u));
        P[4 + i] = f2fma(S,  u, f2mul(C, w));
    }
}

__device__ __forceinline__ void ry_shfl(u64* P, int t, int m, float c, float s) {
    u64 C = bc(c), SE = bc((t & m) ? s : -s);
#pragma unroll
    for (int j = 0; j < 8; j++) {
        u64 w = __shfl_xor_sync(0xffffffffu, P[j], m);
        P[j] = f2fma(SE, w, f2mul(C, P[j]));
    }
}

// Fused RY on two shfl lanes (masks m1, m2): 3 shfl + 4 FMA2 per u64.
__device__ __forceinline__ void ry_shfl2(u64* P, int t, int m1, int m2,
                                         float c1, float s1, float c2, float s2) {
    float se1 = (t & m1) ? s1 : -s1;
    float se2 = (t & m2) ? s2 : -s2;
    u64 k00 = bc(c1 * c2), k01 = bc(c1 * se2);
    u64 k10 = bc(se1 * c2), k11 = bc(se1 * se2);
#pragma unroll
    for (int j = 0; j < 8; j++) {
        u64 v   = P[j];
        u64 w2  = __shfl_xor_sync(0xffffffffu, v, m2);
        u64 w1  = __shfl_xor_sync(0xffffffffu, v, m1);
        u64 w12 = __shfl_xor_sync(0xffffffffu, v, m1 | m2);
        P[j] = f2fma(k00, v,
               f2fma(k01, w2,
               f2fma(k10, w1, f2mul(k11, w12))));
    }
}

// Combined RY(lane0)*RY(lane1) (t bits 7,6): 4-way gather within warp groups
// {w, w^2, w^4, w^6} -> 128-thread named barrier, id 13+(w&1).
__device__ __forceinline__ void ry_smem4(u64* P, int t,
                                         float c0, float s0, float c1, float s1,
                                         u64* X) {
    const int gid = 13 + ((t >> 5) & 1);
#pragma unroll
    for (int j = 0; j < 8; j++) X[t * STq + j] = P[j];
    NBAR128(gid);
    int a  = (t >> 7) & 1;
    int bb = (t >> 6) & 1;
    float r0a0 = a  ? s0 : c0;
    float r0a1 = a  ? c0 : -s0;
    float r1b0 = bb ? s1 : c1;
    float r1b1 = bb ? c1 : -s1;
    u64 k00 = bc(r0a0 * r1b0), k01 = bc(r0a0 * r1b1);
    u64 k10 = bc(r0a1 * r1b0), k11 = bc(r0a1 * r1b1);
    int base = t & 63;
    const u64* x00 = X + base * STq;
    const u64* x01 = X + (base | 64)  * STq;
    const u64* x10 = X + (base | 128) * STq;
    const u64* x11 = X + (base | 192) * STq;
#pragma unroll
    for (int j = 0; j < 8; j++)
        P[j] = f2fma(k00, x00[j],
               f2fma(k01, x01[j],
               f2fma(k10, x10[j], f2mul(k11, x11[j]))));
    NBAR128(gid);   // group read-complete before ry_smem1 overwrites exch
}

// RY on lane2 (t bit5): pair {w, w^1} exchange, id 9+((w>>1)&3). No trailing
// bar: next-stage exch write by w is ordered after partner's read via the
// stage's bit5 ciy barrier (same pair).
__device__ __forceinline__ void ry_smem1(u64* P, int t, float c, float s, u64* X) {
    const int pid = 9 + ((t >> 6) & 3);
#pragma unroll
    for (int j = 0; j < 8; j++) X[t * STq + j] = P[j];
    NBAR64(pid);
    const u64* xp = X + (t ^ 32) * STq;
    u64 C = bc(c), SE = bc((t & 32) ? s : -s);
#pragma unroll
    for (int j = 0; j < 8; j++) P[j] = f2fma(SE, xp[j], f2mul(C, P[j]));
}

// ---- CiY pieces (ctrl anc1: odd j) ----

__device__ __forceinline__ void ciy_lane9(u64* P) {
#pragma unroll
    for (int j = 1; j < 8; j += 2) {
        float lo, hi; upk(P[j], lo, hi);
        P[j] = pk(hi, -lo);
    }
}

__device__ __forceinline__ void ciy_lane8(u64* P) {
#pragma unroll
    for (int i = 1; i < 4; i += 2) {
        u64 p0 = P[i];
        P[i] = P[4 + i];
        P[4 + i] = f2neg(p0);
    }
}

__device__ __forceinline__ void ciy_shfl(u64* P, int t, int m) {
    u64 sgn = (t & m) ? SGN2 : 0ULL;
#pragma unroll
    for (int j = 1; j < 8; j += 2) {
        u64 w = __shfl_xor_sync(0xffffffffu, P[j], m);
        P[j] = w ^ sgn;
    }
}

// Cross-warp CiY: dedicated buffer, one pair barrier.
__device__ __forceinline__ void ciy_nb(u64* P, int t, int m, u64* buf, int id) {
#pragma unroll
    for (int j = 1; j < 8; j += 2) buf[t * CPq + (j >> 1)] = P[j];
    NBAR64(id);
    const u64* p = buf + (t ^ m) * CPq;
    u64 sgn = (t & m) ? SGN2 : 0ULL;
#pragma unroll
    for (int j = 1; j < 8; j += 2) P[j] = p[j >> 1] ^ sgn;
}

// ---- fused neuron ops (packed over lane9; loop over a = lane8 bit) ----

__device__ __forceinline__ void applyT(u64* P, float cb, float sb,
                                       const u64* DC, const u64* DS) {
    u64 CB = bc(cb), SB = bc(sb), NSB = bc(-sb);
#pragma unroll
    for (int a = 0; a < 2; a++) {
        u64 C  = f2fma(NSB, DS[a], f2mul(CB, DC[a]));
        u64 S  = f2fma(SB,  DC[a], f2mul(CB, DS[a]));
        u64 NS = f2neg(S);
        u64 x0 = P[4*a+0], x1 = P[4*a+1], x2 = P[4*a+2], x3 = P[4*a+3];
        P[4*a+0] = f2fma(S,  x3, f2mul(C, x0));
        P[4*a+1] = f2fma(NS, x2, f2mul(C, x1));
        P[4*a+2] = f2fma(S,  x1, f2mul(C, x2));
        P[4*a+3] = f2fma(NS, x0, f2mul(C, x3));
    }
}

__device__ __forceinline__ void applyE(u64* P, float cb, float sb,
                                       const u64* DC, const u64* DS) {
    u64 CB = bc(cb), SB = bc(sb), NSB = bc(-sb);
#pragma unroll
    for (int a = 0; a < 2; a++) {
        u64 C  = f2fma(NSB, DS[a], f2mul(CB, DC[a]));
        u64 S  = f2fma(SB,  DC[a], f2mul(CB, DS[a]));
        u64 NS = f2neg(S);
        u64 x0 = P[4*a+0], x1 = P[4*a+1], x2 = P[4*a+2], x3 = P[4*a+3];
        P[4*a+0] = f2fma(NS, x2, f2mul(C, x0));
        P[4*a+1] = f2fma(NS, x3, f2mul(C, x1));
        P[4*a+2] = f2fma(S,  x1, f2mul(C, x3));
        P[4*a+3] = f2neg(f2fma(S, x0, f2mul(C, x2)));
    }
}

__device__ __forceinline__ void applyF(u64* P, float cb, float sb,
                                       const u64* DC, const u64* DS) {
    u64 CB = bc(cb), SB = bc(sb), NSB = bc(-sb);
#pragma unroll
    for (int a = 0; a < 2; a++) {
        u64 C  = f2fma(NSB, DS[a], f2mul(CB, DC[a]));
        u64 S  = f2fma(SB,  DC[a], f2mul(CB, DS[a]));
        u64 NS = f2neg(S);
        u64 x0 = P[4*a+0], x1 = P[4*a+1], x2 = P[4*a+2], x3 = P[4*a+3];
        P[4*a+0] = f2fma(NS, x3, f2mul(C, x0));
        P[4*a+1] = f2fma(S,  x2, f2mul(C, x1));
        P[4*a+2] = f2neg(f2fma(S, x0, f2mul(C, x3)));
        P[4*a+3] = f2fma(NS, x1, f2mul(C, x2));
    }
}

__device__ __forceinline__ void applyG_se(u64* P, u64 C, u64 SE0, u64 SE1) {
    u64 NSE0 = f2neg(SE0), NSE1 = f2neg(SE1);
    {
        u64 x1 = P[1], x3 = P[3];
        P[1] = f2fma(NSE0, x3, f2mul(C, x1));
        P[3] = f2fma(SE0,  x1, f2mul(C, x3));
    }
    {
        u64 x1 = P[5], x3 = P[7];
        P[5] = f2fma(NSE1, x3, f2mul(C, x1));
        P[7] = f2fma(SE1,  x1, f2mul(C, x3));
    }
}

// angle-vector spec tables
__device__ constexpr int aIdx[NIDX] = {1,2,3,4,5,6,7,8,9, 11,12,13,14,15,16,17,18,19, 0, 10, 9, 19};
__device__ constexpr int bIdx[NIDX] = {0,1,2,3,4,5,6,7,8, 10,11,12,13,14,15,16,17,18, -1,-1,-1,-1};

__global__ void __launch_bounds__(NTH, 1) rvqe_kernel(
    const int*   __restrict__ inputs,   // (64, 9, 6) int32
    const float* __restrict__ ua,       // (2, 10)
    const float* __restrict__ nth,      // (2, 10, 11)
    float*       __restrict__ out,
    int out_size)
{
    extern __shared__ u64 dyn[];
    u64* exch = dyn + OFF_EXCH;
    u64* p128 = dyn + OFF_P128;
    u64* p64b = dyn + OFF_P64;
    u64* p32b = dyn + OFF_P32;

    __shared__ float uc[20], us[20];
    __shared__ u64   DC2[NIDX][2], DS2[NIDX][2];
    __shared__ float gc_sm[20], gs_sm[20];
    __shared__ u64   se9p[2];
    __shared__ float probs_sm[64];
    __shared__ int   tIdx[TT];

    const int t = threadIdx.x;
    const int b = blockIdx.x;
    const int w = t >> 5;
    const int* inb = inputs + b * TT * 6;

    const int id128 = 1 + (w & 3);                      // pair {w, w^4}
    const int id64  = 5 + ((w & 1) | ((w >> 1) & 2));   // pair {w, w^2}
    const int id32  = 9 + ((w >> 1) & 3);               // pair {w, w^1}

    // ---- precompute ----
    if (t < 20) {
        float c, s; sincosf(0.5f * ua[t], &s, &c);
        uc[t] = c; us[t] = s;
        float cg, sg; sincosf(0.5f * nth[t * 11 + (t % 10)], &sg, &cg);
        gc_sm[t] = cg; gs_sm[t] = sg;
        if ((t % 10) == 9) se9p[t / 10] = pk(-sg, sg);
    }
    if (t < NIDX * 2) {
        int idx = t >> 1, a = t & 1;
        const float* A = nth + aIdx[idx] * 11;
        const float* Bp = (bIdx[idx] >= 0) ? (nth + bIdx[idx] * 11) : nullptr;
        float d8 = A[8] - (Bp ? Bp[8] : 0.f);
        float d9 = A[9] - (Bp ? Bp[9] : 0.f);
        float dlo = a ? d8 : 0.f;
        float dhi = dlo + d9;
        float cl, sl, ch, sh;
        sincosf(0.5f * dlo, &sl, &cl);
        sincosf(0.5f * dhi, &sh, &ch);
        DC2[idx][a] = pk(cl, ch);
        DS2[idx][a] = pk(sl, sh);
    }
    if (t < TT) {
        int idx = 0;
#pragma unroll
        for (int i = 0; i < 6; i++) idx |= (inb[t * 6 + i] & 1) << (5 - i);
        tIdx[t] = idx;
    }

    float cbs[NIDX], sbs[NIDX];
#pragma unroll
    for (int idx = 0; idx < NIDX; idx++) {
        const float* A = nth + aIdx[idx] * 11;
        const float* Bp = (bIdx[idx] >= 0) ? (nth + bIdx[idx] * 11) : nullptr;
        float base = A[10] - (Bp ? Bp[10] : 0.f);
#pragma unroll
        for (int i = 0; i < 8; i++)
            if ((t >> (7 - i)) & 1) base += A[i] - (Bp ? Bp[i] : 0.f);
        float c, s; sincosf(0.5f * base, &s, &c);
        cbs[idx] = c; sbs[idx] = s;
    }
    __syncthreads();

    // ---- init state ----
    u64 P[8];
#pragma unroll
    for (int j = 0; j < 8; j++) P[j] = 0ULL;
    if (t == (tIdx[0] << 2)) P[0] = pk(1.f, 0.f);

    for (int step = 0; step < NSTEP; step++) {
#pragma unroll
        for (int s = 0; s < 2; s++) {
            const float* ucc = uc + s * 10;
            const float* uss = us + s * 10;
            // stage RYs
            ry_lane8(P, ucc[8], uss[8]);
            {
                u64 C9 = bc(ucc[9]);
                u64 SW = pk(-uss[9], uss[9]);
                ry_lane9(P, C9, SW);
            }
            ry_shfl2(P, t, 16, 8, ucc[3], uss[3], ucc[4], uss[4]);
            ry_shfl2(P, t, 4, 2, ucc[5], uss[5], ucc[6], uss[6]);
            ry_shfl(P, t, 1, ucc[7], uss[7]);
            ry_smem4(P, t, ucc[0], uss[0], ucc[1], uss[1], exch);
            ry_smem1(P, t, ucc[2], uss[2], exch);

            // neuron chain: E C0 G0 T' C1 G1 ... T' C9 G9 F
            applyE(P, cbs[18 + s], sbs[18 + s], DC2[18 + s], DS2[18 + s]);
            ciy_nb(P, t, 128, p128, id128);             // C0 (lane0 = t bit7)
            {
                float sg = ((t >> 7) & 1) ? gs_sm[s * 10] : -gs_sm[s * 10];
                u64 SE = bc(sg);
                applyG_se(P, bc(gc_sm[s * 10]), SE, SE);
            }
#pragma unroll
            for (int n = 1; n < 10; n++) {
                int di = s * 9 + n - 1;
                applyT(P, cbs[di], sbs[di], DC2[di], DS2[di]);
                if (n == 9) {
                    ciy_lane9(P);
                } else if (n == 8) {
                    ciy_lane8(P);
                } else if (n >= 3) {
                    ciy_shfl(P, t, 1 << (7 - n));
                } else if (n == 1) {
                    ciy_nb(P, t, 64, p64b, id64);
                } else {
                    ciy_nb(P, t, 32, p32b, id32);
                }
                int gi = s * 10 + n;
                u64 C = bc(gc_sm[gi]);
                if (n <= 7) {
                    float sg = ((t >> (7 - n)) & 1) ? gs_sm[gi] : -gs_sm[gi];
                    u64 SE = bc(sg);
                    applyG_se(P, C, SE, SE);
                } else if (n == 8) {
                    u64 SE1 = bc(gs_sm[gi]);
                    applyG_se(P, C, f2neg(SE1), SE1);
                } else {
                    u64 SE = se9p[s];
                    applyG_se(P, C, SE, SE);
                }
            }
            applyF(P, cbs[20 + s], sbs[20 + s], DC2[20 + s], DS2[20 + s]);
        }

        // ---- probs ----
        u64 acc = 0ULL;
#pragma unroll
        for (int j = 0; j < 8; j++) acc = f2fma(P[j], P[j], acc);
        float alo, ahi; upk(acc, alo, ahi);
        float ssq = alo + ahi;
        ssq += __shfl_xor_sync(0xffffffffu, ssq, 1);
        ssq += __shfl_xor_sync(0xffffffffu, ssq, 2);
        if (!(t & 3)) {
            probs_sm[t >> 2] = ssq;
            out[(b * NSTEP + step) * 64 + (t >> 2)] = ssq;
        }
        __syncthreads();

        // ---- project + normalize ----
        int tj = tIdx[step + 1];
        float invn = 1.0f / sqrtf(probs_sm[tj]);
        if ((t >> 2) == tj) {
            u64 INV = bc(invn);
#pragma unroll
            for (int j = 0; j < 8; j++) P[j] = f2mul(INV, P[j]);
        } else {
#pragma unroll
            for (int j = 0; j < 8; j++) P[j] = 0ULL;
        }
    }

    // ---- second tuple output: measured = inputs[:,1:] as float ----
    if (out_size > 32768 && t < 48) {
        out[32768 + b * 48 + t] = (float)inb[6 + t];
    }
}

} // namespace

extern "C" void kernel_launch(void* const* d_in, const int* in_sizes, int n_in,
                              void* d_out, int out_size) {
    const int*   inputs = nullptr;
    const float* ua     = nullptr;
    const float* nth    = nullptr;
    for (int i = 0; i < n_in; i++) {
        if (in_sizes[i] == 3456)      inputs = (const int*)d_in[i];
        else if (in_sizes[i] == 20)   ua     = (const float*)d_in[i];
        else if (in_sizes[i] == 220)  nth    = (const float*)d_in[i];
    }
    const int dyn_bytes = DYN_U64 * 8;   // 49152
    cudaFuncSetAttribute(rvqe_kernel, cudaFuncAttributeMaxDynamicSharedMemorySize,
                         dyn_bytes);
    rvqe_kernel<<<64, NTH, dyn_bytes>>>(inputs, ua, nth, (float*)d_out, out_size);
}